// round 17
// baseline (speedup 1.0000x reference)
#include <cuda_runtime.h>
#include <cuda_bf16.h>
#include <cstdint>

// ---------------------------------------------------------------------------
// NoteAxis 2-layer LSTM (B=4096, U=128, 128 steps) — warp-level mma.sync bf16,
// 3-term hi/lo split (fp32-grade accuracy, measured 3.7e-7).
// R16: 256 CTAs x 256 threads, 16 batch rows per CTA -> TWO independent CTAs
// per SM. Their barrier/load/epilogue phases interleave, keeping the HMMA
// pipe busy while the other CTA syncs. Ring back to 3 x 16KB pieces.
// Math and weight images identical to R14/R15.
// ---------------------------------------------------------------------------

#define NSTEP 128
#define FDIM  127
#define BT    16
#define NCTA  256
#define NT    256

#define ABLK  4352      // one A block: 16 rows x 272 bytes (128 bf16 + pad)
#define ASTR  272
#define PIECE 16384     // one weight piece: 1 kchunk x 64 ntiles x 256B
#define NSEQ  64        // pieces per step (2 layers x 32)

// smem byte offsets
#define SM_A     0              // 6 blocks: Xhi Xlo H0hi H0lo H1hi H1lo
#define SM_RING  26112          // 3 x 16KB
#define SM_BIAS  75264          // 2 x 512 floats (unit-major n)
#define SM_WOUT  79360          // 128 floats
#define SM_BOUT  79872
#define SM_PART  79888          // 8 x 16 floats
#define SMEM_SZ  80400

// ---------------- persistent device scratch --------------------------------
// fragment-major weights: u64 index = piece*2048 + gnt*32 + lane
// piece s: L=s>>5, T=(s>>4)&1 (0=hi,1=lo), kc=s&15
__device__ unsigned long long g_Bf[64 * 2048];
__device__ float g_biasn[1024];     // [L][n], n = 4u+g
__device__ float g_wout[128], g_bout[1];

// ---------------------------------------------------------------------------
__global__ void noteaxis_prep(const float* __restrict__ wih0, const float* __restrict__ whh0,
                              const float* __restrict__ bih0, const float* __restrict__ bhh0,
                              const float* __restrict__ wih1, const float* __restrict__ whh1,
                              const float* __restrict__ bih1, const float* __restrict__ bhh1,
                              const float* __restrict__ wout, const float* __restrict__ bout)
{
    int idx = blockIdx.x * blockDim.x + threadIdx.x;
    if (idx < 64 * 2048) {
        int s = idx >> 11, r = idx & 2047;
        int gnt = r >> 5, lane = r & 31;
        int L = s >> 5, T = (s >> 4) & 1, kc = s & 15;
        int n = gnt * 8 + (lane >> 2);
        int u = n >> 2, g = n & 3, col = g * 128 + u;   // PyTorch gate-major col
        const float* wih = L ? wih1 : wih0;
        const float* whh = L ? whh1 : whh0;
        unsigned long long v = 0;
#pragma unroll
        for (int rg = 0; rg < 2; ++rg) {
            unsigned int pk = 0;
#pragma unroll
            for (int half = 0; half < 2; ++half) {
                int k = kc * 16 + (lane & 3) * 2 + rg * 8 + half;
                float w = (k < 128) ? wih[col * 128 + k] : whh[col * 128 + (k - 128)];
                __nv_bfloat16 hi = __float2bfloat16_rn(w);
                __nv_bfloat16 e = T ? __float2bfloat16_rn(w - __bfloat162float(hi)) : hi;
                pk |= (unsigned int)__bfloat16_as_ushort(e) << (16 * half);
            }
            v |= (unsigned long long)pk << (32 * rg);
        }
        g_Bf[idx] = v;
    }
    if (idx < 1024) {
        int L = idx >> 9, n = idx & 511;
        int u = n >> 2, g = n & 3, col = g * 128 + u;
        g_biasn[idx] = L ? (bih1[col] + bhh1[col]) : (bih0[col] + bhh0[col]);
    }
    if (idx < 128) g_wout[idx] = wout[idx];
    if (idx == 0)  g_bout[0] = bout[0];
}

// ---------------------------------------------------------------------------
__device__ __forceinline__ float ftanh_(float x) {
    float r; asm("tanh.approx.f32 %0, %1;" : "=f"(r) : "f"(x)); return r;
}
__device__ __forceinline__ float fsig(float x) { return fmaf(0.5f, ftanh_(0.5f * x), 0.5f); }

__device__ __forceinline__ void prefetch_piece(uint32_t dst, const char* src, int tid) {
    uint32_t d = dst + tid * 16;
    src += tid * 16;
#pragma unroll
    for (int i = 0; i < 4; ++i) {   // 256 thr x 4 x 16B = 16KB
        asm volatile("cp.async.cg.shared.global [%0], [%1], 16;" :: "r"(d), "l"(src) : "memory");
        d += NT * 16; src += NT * 16;
    }
    asm volatile("cp.async.commit_group;" ::: "memory");
}

__device__ __forceinline__ void ldA(uint32_t ad, uint32_t (&a)[4]) {
    asm volatile("ld.shared.b32 %0, [%1];" : "=r"(a[0]) : "r"(ad));
    asm volatile("ld.shared.b32 %0, [%1];" : "=r"(a[1]) : "r"(ad + 8 * ASTR));
    asm volatile("ld.shared.b32 %0, [%1];" : "=r"(a[2]) : "r"(ad + 16));
    asm volatile("ld.shared.b32 %0, [%1];" : "=r"(a[3]) : "r"(ad + 8 * ASTR + 16));
}

__device__ __forceinline__ void mma16816(float* c, const uint32_t (&a)[4],
                                         uint32_t b0, uint32_t b1) {
    asm volatile("mma.sync.aligned.m16n8k16.row.col.f32.bf16.bf16.f32 "
                 "{%0,%1,%2,%3}, {%4,%5,%6,%7}, {%8,%9}, {%0,%1,%2,%3};"
                 : "+f"(c[0]), "+f"(c[1]), "+f"(c[2]), "+f"(c[3])
                 : "r"(a[0]), "r"(a[1]), "r"(a[2]), "r"(a[3]), "r"(b0), "r"(b1));
}

// ---------------------------------------------------------------------------
__global__ void __launch_bounds__(NT, 2)
noteaxis_lstm(const float* __restrict__ nf, const float* __restrict__ tg,
              float* __restrict__ out)
{
    extern __shared__ __align__(16) char smem[];
    const uint32_t sb = (uint32_t)__cvta_generic_to_shared(smem);
    const int tid = threadIdx.x, warp = tid >> 5, lane = tid & 31;
    const int nq = warp;                 // warp tile: all 16 rows, cols nq*64..
    const int b0 = blockIdx.x * BT;
    const int lr = lane >> 2, lc = lane & 3;

    // zero A blocks (h starts at 0); stage bias/wout/bout
    for (int i = tid; i < 6 * ABLK / 4; i += NT)
        reinterpret_cast<uint32_t*>(smem)[i] = 0u;
    for (int i = tid; i < 1024; i += NT)
        reinterpret_cast<float*>(smem + SM_BIAS)[i] = g_biasn[i];
    if (tid < 128) reinterpret_cast<float*>(smem + SM_WOUT)[tid] = g_wout[tid];
    if (tid == 0)  reinterpret_cast<float*>(smem + SM_BOUT)[0] = g_bout[0];

    const int rowg = lr + 8 * (lane & 1);            // this thread's C row (0..15)
    float cs0[8], cs1[8];
#pragma unroll
    for (int i = 0; i < 8; ++i) { cs0[i] = 0.f; cs1[i] = 0.f; }

    const uint32_t aoff = (uint32_t)(lr * ASTR + lc * 4);
    const uint32_t boff = (uint32_t)(nq * 8 * 256 + lane * 8);   // 8 ntiles/warp

    // prologue: prefetch pieces 0,1
    prefetch_piece(sb + SM_RING, reinterpret_cast<const char*>(g_Bf), tid);
    prefetch_piece(sb + SM_RING + PIECE, reinterpret_cast<const char*>(g_Bf) + PIECE, tid);
    int pseq = 2, gbuf = 0;
    __syncthreads();

    float* part = reinterpret_cast<float*>(smem + SM_PART);

    for (int t = 0; t < NSTEP; ++t) {
        // ---- stage x_t split hi/lo into blocks 0,1 -------------------------
#pragma unroll
        for (int i = 0; i < 8; ++i) {
            int idx = tid + i * NT;          // 0..2047
            int row = idx >> 7, f = idx & 127;
            float v;
            if (f < FDIM) v = nf[((size_t)(b0 + row) * NSTEP + t) * FDIM + f];
            else          v = t ? tg[(size_t)(b0 + row) * NSTEP + t - 1] : 0.f;
            __nv_bfloat16 hi = __float2bfloat16_rn(v);
            __nv_bfloat16 lo = __float2bfloat16_rn(v - __bfloat162float(hi));
            int eo = row * (ASTR / 2) + f;
            reinterpret_cast<__nv_bfloat16*>(smem)[eo] = hi;
            reinterpret_cast<__nv_bfloat16*>(smem + ABLK)[eo] = lo;
        }
        // first piece-barrier below orders staging before GEMM reads

#pragma unroll 1
        for (int L = 0; L < 2; ++L) {
            float acc[32];
#pragma unroll
            for (int i = 0; i < 32; ++i) acc[i] = 0.f;

#pragma unroll 1
            for (int p = 0; p < 32; ++p) {
                asm volatile("cp.async.wait_group 1;" ::: "memory");
                __syncthreads();
                int tbuf = gbuf + 2; if (tbuf >= 3) tbuf -= 3;
                prefetch_piece(sb + SM_RING + (uint32_t)tbuf * PIECE,
                               reinterpret_cast<const char*>(g_Bf) + (size_t)pseq * PIECE, tid);
                pseq = (pseq + 1) & 63;

                const int T = p >> 4, kc = p & 15;
                const int hiblk = (L == 0) ? (kc < 8 ? 0 : 2) : (kc < 8 ? 2 : 4);
                const uint32_t kb = (uint32_t)((kc & 7) * 32);
                uint32_t aH[4], aL[4];
                ldA(sb + (uint32_t)hiblk * ABLK + aoff + kb, aH);
                if (T == 0) ldA(sb + (uint32_t)(hiblk + 1) * ABLK + aoff + kb, aL);

                uint32_t bb = sb + SM_RING + (uint32_t)gbuf * PIECE + boff;
#pragma unroll
                for (int nt = 0; nt < 8; ++nt) {
                    uint32_t w0, w1;
                    asm volatile("ld.shared.v2.u32 {%0, %1}, [%2];"
                                 : "=r"(w0), "=r"(w1) : "r"(bb + (uint32_t)nt * 256));
                    mma16816(acc + nt * 4, aH, w0, w1);
                    if (T == 0) mma16816(acc + nt * 4, aL, w0, w1);
                }
                if (++gbuf == 3) gbuf = 0;
            }
            __syncthreads();   // all GEMM reads done before epilogue h writes

            // ---------------- epilogue: gates -> cells -> h ----------------
            const float* bias = reinterpret_cast<const float*>(smem + SM_BIAS) + L * 512;
            const float* wo = reinterpret_cast<const float*>(smem + SM_WOUT);
            float* cs = L ? cs1 : cs0;
            __nv_bfloat16* Hhi = reinterpret_cast<__nv_bfloat16*>(smem + (size_t)(2 + 2 * L) * ABLK);
            __nv_bfloat16* Hlo = reinterpret_cast<__nv_bfloat16*>(smem + (size_t)(3 + 2 * L) * ABLK);
            float dot = 0.f;
#pragma unroll
            for (int nt = 0; nt < 8; ++nt) {
                float c0 = acc[nt * 4], c1 = acc[nt * 4 + 1];
                float c2 = acc[nt * 4 + 2], c3 = acc[nt * 4 + 3];
                int n0 = nq * 64 + nt * 8 + 2 * lc;
                float2 bb2 = *reinterpret_cast<const float2*>(bias + n0);
                c0 += bb2.x; c1 += bb2.y; c2 += bb2.x; c3 += bb2.y;
                bool odd = (lane & 1);
                float v1 = __shfl_xor_sync(0xffffffffu, odd ? c0 : c2, 1);
                float v2 = __shfl_xor_sync(0xffffffffu, odd ? c1 : c3, 1);
                float gi_ = odd ? v1 : c0;
                float gf  = odd ? v2 : c1;
                float gg  = odd ? c2 : v1;
                float go  = odd ? c3 : v2;
                float c = fsig(gf) * cs[nt] + fsig(gi_) * ftanh_(gg);
                cs[nt] = c;
                float h = fsig(go) * ftanh_(c);
                int u = nq * 16 + nt * 2 + (lc >> 1);
                __nv_bfloat16 hh = __float2bfloat16_rn(h);
                __nv_bfloat16 hl = __float2bfloat16_rn(h - __bfloat162float(hh));
                int eo = rowg * (ASTR / 2) + u;
                Hhi[eo] = hh;
                Hlo[eo] = hl;
                if (L) dot = fmaf(h, wo[u], dot);
            }
            if (L) {
                dot += __shfl_xor_sync(0xffffffffu, dot, 2);
                if ((lane & 2) == 0) part[nq * 16 + rowg] = dot;
            }
            // next loop's first piece-barrier orders h writes before reads
        }

        __syncthreads();   // h1 + partials visible
        if (tid < 16) {
            float s = reinterpret_cast<const float*>(smem + SM_BOUT)[0];
#pragma unroll
            for (int j = 0; j < 8; ++j) s += part[j * 16 + tid];
            out[(size_t)(b0 + tid) * NSTEP + t] = fsig(s);
        }
        // next-step x staging writes blocks 0,1 only; the first piece-barrier
        // of the next step orders it against all readers.
    }
}

// ---------------------------------------------------------------------------
extern "C" void kernel_launch(void* const* d_in, const int* in_sizes, int n_in,
                              void* d_out, int out_size)
{
    const float* nf   = (const float*)d_in[0];
    const float* tg   = (const float*)d_in[1];
    const float* wih0 = (const float*)d_in[2];
    const float* whh0 = (const float*)d_in[3];
    const float* bih0 = (const float*)d_in[4];
    const float* bhh0 = (const float*)d_in[5];
    const float* wih1 = (const float*)d_in[6];
    const float* whh1 = (const float*)d_in[7];
    const float* bih1 = (const float*)d_in[8];
    const float* bhh1 = (const float*)d_in[9];
    const float* wout = (const float*)d_in[10];
    const float* bout = (const float*)d_in[11];
    float* out = (float*)d_out;

    cudaFuncSetAttribute(noteaxis_lstm, cudaFuncAttributeMaxDynamicSharedMemorySize, SMEM_SZ);

    noteaxis_prep<<<(64 * 2048 + 255) / 256, 256>>>(wih0, whh0, bih0, bhh0,
                                                    wih1, whh1, bih1, bhh1,
                                                    wout, bout);
    noteaxis_lstm<<<NCTA, NT, SMEM_SZ>>>(nf, tg, out);
}